// round 16
// baseline (speedup 1.0000x reference)
#include <cuda_runtime.h>
#include <cstdint>

// 3-level Haar DWT, fully fused: 16 inputs/thread, full 256-bit ld/st,
// register-capped to restore 8 CTAs/SM occupancy (R14 shape + R15 occupancy).
// x: [B, L=16384] fp32. Output: [cA3 (B*2048) | cD3 (B*2048) | cD2 (B*4096) | cD1 (B*8192)]
//
// Per thread t (0 .. B*1024-1), inputs [16t, 16t+16):
//   loads : 2x ld.global.v8.f32
//   stores: cD1 1x st.global.v8.f32, cD2 STG.128, cD3/cA3 STG.64 — all coalesced.
// __launch_bounds__(256, 8) caps regs at 32: d-values are consumed immediately
// after level 1 to keep live ranges short (avoid spills).

__global__ __launch_bounds__(256, 8) void haar3_v8x2(
    const float* __restrict__ in,     // B*16384
    float2* __restrict__ cA3_2,       // B*2048 floats
    float2* __restrict__ cD3_2,       // B*2048 floats
    float4* __restrict__ cD2_4,       // B*4096 floats
    float*  __restrict__ cD1,         // B*8192 floats
    int total)                        // B * 1024
{
    int t = blockIdx.x * blockDim.x + threadIdx.x;
    if (t >= total) return;

    const float S  = 0.70710678118654752440f;   // 2^-1/2
    const float S2 = 0.5f;
    const float S3 = 0.35355339059327376220f;   // 2^-3/2

    const float* p = in + (size_t)t * 16;

    float x0,x1,x2,x3,x4,x5,x6,x7,x8,x9,x10,x11,x12,x13,x14,x15;
    asm volatile("ld.global.v8.f32 {%0,%1,%2,%3,%4,%5,%6,%7}, [%8];"
        : "=f"(x0),"=f"(x1),"=f"(x2),"=f"(x3),
          "=f"(x4),"=f"(x5),"=f"(x6),"=f"(x7)
        : "l"(p));
    asm volatile("ld.global.v8.f32 {%0,%1,%2,%3,%4,%5,%6,%7}, [%8];"
        : "=f"(x8),"=f"(x9),"=f"(x10),"=f"(x11),
          "=f"(x12),"=f"(x13),"=f"(x14),"=f"(x15)
        : "l"(p + 8));

    // ---- level 1: pair sums/diffs; scale diffs immediately (short live range) ----
    float a0 = x0  + x1,  d0 = S * (x0  - x1);
    float a1 = x2  + x3,  d1 = S * (x2  - x3);
    float a2 = x4  + x5,  d2 = S * (x4  - x5);
    float a3 = x6  + x7,  d3 = S * (x6  - x7);
    float a4 = x8  + x9,  d4 = S * (x8  - x9);
    float a5 = x10 + x11, d5 = S * (x10 - x11);
    float a6 = x12 + x13, d6 = S * (x12 - x13);
    float a7 = x14 + x15, d7 = S * (x14 - x15);

    // store cD1 first — frees d0..d7
    float* q = cD1 + (size_t)t * 8;
    asm volatile("st.global.v8.f32 [%8], {%0,%1,%2,%3,%4,%5,%6,%7};"
        :: "f"(d0),"f"(d1),"f"(d2),"f"(d3),
           "f"(d4),"f"(d5),"f"(d6),"f"(d7),
           "l"(q) : "memory");

    // ---- level 2 ----
    float A0 = a0 + a1, D0 = a0 - a1;
    float A1 = a2 + a3, D1 = a2 - a3;
    float A2 = a4 + a5, D2 = a4 - a5;
    float A3 = a6 + a7, D3 = a6 - a7;

    cD2_4[t] = make_float4(S2 * D0, S2 * D1, S2 * D2, S2 * D3);

    // ---- level 3 ----
    cD3_2[t] = make_float2(S3 * (A0 - A1), S3 * (A2 - A3));
    cA3_2[t] = make_float2(S3 * (A0 + A1), S3 * (A2 + A3));
}

extern "C" void kernel_launch(void* const* d_in, const int* in_sizes, int n_in,
                              void* d_out, int out_size)
{
    const float* x = (const float*)d_in[0];
    float* out = (float*)d_out;

    const int L = 16384;
    const int B = in_sizes[0] / L;      // 2048
    const int total = B * (L / 16);     // B * 1024

    // Output layout: [cA3 | cD3 | cD2 | cD1]
    float2* cA3 = (float2*)out;
    float2* cD3 = (float2*)(out + (size_t)B * (L / 8));      // + B*2048
    float4* cD2 = (float4*)(out + (size_t)2 * B * (L / 8));  // + B*4096
    float*  cD1 = out + (size_t)B * (L / 2);                 // + B*8192

    int threads = 256;
    int blocks = (total + threads - 1) / threads;
    haar3_v8x2<<<blocks, threads>>>(x, cA3, cD3, cD2, cD1, total);
}